// round 15
// baseline (speedup 1.0000x reference)
#include <cuda_runtime.h>
#include <cuda_fp16.h>
#include <math.h>
#include <stdint.h>

// ===========================================================================
// GNN over fixed 4-node graph, B=32768 (M = 4B = 131072 rows).
// L2-L4 GEMM: mma.sync fp16->fp32, CTA 128x128, 4 warps (2x2) of 64x64,
// 2 CTAs/SM, 3-stage cp.async. Weight tiles interleave [Wl|Wr] for the SAME
// output features, so the SAGE mix (y = M.Pl + Pr + b) fuses into the GEMM
// epilogue; per-row ssq partials go to a race-free [M][8] buffer; a light
// normalize kernel (or sage_fc for L4) applies rsqrt+relu.
// Dedicated L1 kernel (fp32 x direct, fused GCN).
// ===========================================================================

#define MAXB 32768
#define PADK 72
#define TILE_A (128 * PADK * 2)
#define TILE_W (128 * PADK * 2)
#define STAGE_B (TILE_A + TILE_W)
#define STAGES 3
#define SMEM_BYTES (STAGES * STAGE_B)   // 110592 -> 2 CTAs/SM
#define PADE 136
#define NTHREADS 128
#define OFF_SRED 65536                  // 128 floats inside pipeline smem

#define L1_OFFX 0
#define L1_OFFA 34816
#define L1_OFFW (34816 + 18432)
#define L1_SMEM (L1_OFFW + 18432)

__device__ float g_A[16];
__device__ float g_M[16];
__device__ __align__(16) __half g_Pf[(size_t)MAXB * 4 * 1024];   // y buffers
__device__ __align__(16) __half g_hf[(size_t)MAXB * 4 * 1024];   // h buffers
__device__ __align__(16) __half g_wt[1507328];
__device__ __align__(16) float  g_part[(size_t)MAXB * 4 * 8];    // ssq partials

// ---------------------------------------------------------------------------
__device__ __forceinline__ uint32_t smem_u32(const void* p) {
    uint32_t a;
    asm("{ .reg .u64 t; cvta.to.shared.u64 t, %1; cvt.u32.u64 %0, t; }"
        : "=r"(a) : "l"(p));
    return a;
}
__device__ __forceinline__ void ldsm_x4(uint32_t (&r)[4], uint32_t addr) {
    asm volatile("ldmatrix.sync.aligned.m8n8.x4.shared.b16 {%0,%1,%2,%3}, [%4];"
                 : "=r"(r[0]), "=r"(r[1]), "=r"(r[2]), "=r"(r[3]) : "r"(addr));
}
__device__ __forceinline__ void ldsm_x2(uint32_t (&r)[2], uint32_t addr) {
    asm volatile("ldmatrix.sync.aligned.m8n8.x2.shared.b16 {%0,%1}, [%2];"
                 : "=r"(r[0]), "=r"(r[1]) : "r"(addr));
}
__device__ __forceinline__ void mma_f16(float (&d)[4], const uint32_t (&a)[4],
                                        uint32_t b0, uint32_t b1) {
    asm volatile(
        "mma.sync.aligned.m16n8k16.row.col.f32.f16.f16.f32 "
        "{%0,%1,%2,%3}, {%4,%5,%6,%7}, {%8,%9}, {%0,%1,%2,%3};"
        : "+f"(d[0]), "+f"(d[1]), "+f"(d[2]), "+f"(d[3])
        : "r"(a[0]), "r"(a[1]), "r"(a[2]), "r"(a[3]), "r"(b0), "r"(b1));
}
__device__ __forceinline__ void cp_async16(uint32_t dst, const void* src) {
    asm volatile("cp.async.cg.shared.global [%0], [%1], 16;"
                 :: "r"(dst), "l"(src));
}
#define CP_COMMIT() asm volatile("cp.async.commit_group;" ::: "memory")
#define CP_WAIT0()  asm volatile("cp.async.wait_group 0;" ::: "memory")
#define CP_WAIT1()  asm volatile("cp.async.wait_group 1;" ::: "memory")

__device__ __forceinline__ uint32_t h2pack(float a, float b) {
    __half2 h = __floats2half2_rn(a, b);
    return *(uint32_t*)&h;
}
__device__ __forceinline__ float4 load_h4(const __half* H, size_t e) {
    uint2 u = *(const uint2*)(H + e);
    __half2 p0 = *(__half2*)&u.x, p1 = *(__half2*)&u.y;
    float2 a = __half22float2(p0), b = __half22float2(p1);
    return make_float4(a.x, a.y, b.x, b.y);
}

// ---------------------------------------------------------------------------
__global__ void build_graph_kernel(const void* __restrict__ ei_raw, int E)
{
    if (threadIdx.x != 0 || blockIdx.x != 0) return;
    const long long* e64 = (const long long*)ei_raw;
    const int*       e32 = (const int*)ei_raw;
    bool is64 = true;
    for (int e = 0; e < E; ++e) {
        long long v = e64[e];
        if (v < 0 || v >= 4) { is64 = false; break; }
    }
    int src[64], dst[64];
    for (int e = 0; e < E; ++e) {
        if (is64) { src[e] = (int)e64[e]; dst[e] = (int)e64[E + e]; }
        else      { src[e] = e32[e];      dst[e] = e32[E + e]; }
    }
    float degG[4] = {1.f, 1.f, 1.f, 1.f};
    float cntS[4] = {0.f, 0.f, 0.f, 0.f};
    for (int e = 0; e < E; ++e) { degG[dst[e]] += 1.f; cntS[dst[e]] += 1.f; }
    float dinv[4];
    #pragma unroll
    for (int n = 0; n < 4; ++n) dinv[n] = rsqrtf(degG[n]);
    float A[16], M[16];
    #pragma unroll
    for (int i = 0; i < 16; ++i) { A[i] = 0.f; M[i] = 0.f; }
    for (int e = 0; e < E; ++e) {
        int s = src[e], d = dst[e];
        A[d * 4 + s] += dinv[s] * dinv[d];
        M[d * 4 + s] += 1.f / fmaxf(cntS[d], 1.f);
    }
    #pragma unroll
    for (int n = 0; n < 4; ++n) A[n * 4 + n] += dinv[n] * dinv[n];
    #pragma unroll
    for (int i = 0; i < 16; ++i) { g_A[i] = A[i]; g_M[i] = M[i]; }
}

// ---------------------------------------------------------------------------
// Weight prep. W1: plain [N][K0]. SAGE layers: interleaved 64-row blocks:
// Wl (k,f) -> row (f/64)*128 + (f%64);  Wr (k,f) -> row (f/64)*128 + 64 + (f%64).
// ---------------------------------------------------------------------------
__global__ void prep_all_kernel(const float* __restrict__ W1,
                                const float* __restrict__ Wl2,
                                const float* __restrict__ Wr2,
                                const float* __restrict__ Wl3,
                                const float* __restrict__ Wr3,
                                const float* __restrict__ Wl4,
                                const float* __restrict__ Wr4)
{
    long long idx = (long long)blockIdx.x * 256 + threadIdx.x;
    if (idx >= 1507328LL) return;
    const float* W; int K0, N; size_t dst; long long rel; int part;
    if      (idx < 65536)   { W = W1;  K0 = 64;   N = 1024; dst = 0;       rel = idx;           part = -1; }
    else if (idx < 589824)  { W = Wl2; K0 = 1024; N = 512;  dst = 65536;   rel = idx - 65536;   part = 0; }
    else if (idx < 1114112) { W = Wr2; K0 = 1024; N = 512;  dst = 65536;   rel = idx - 589824;  part = 1; }
    else if (idx < 1245184) { W = Wl3; K0 = 512;  N = 256;  dst = 1114112; rel = idx - 1114112; part = 0; }
    else if (idx < 1376256) { W = Wr3; K0 = 512;  N = 256;  dst = 1245184 - 131072; rel = idx - 1245184; part = 1; }
    else if (idx < 1441792) { W = Wl4; K0 = 256;  N = 256;  dst = 1376256; rel = idx - 1376256; part = 0; }
    else                    { W = Wr4; K0 = 256;  N = 256;  dst = 1376256; rel = idx - 1441792; part = 1; }
    int k = (int)(rel / N), f = (int)(rel % N);
    size_t n_new;
    if (part < 0) n_new = (size_t)f;                               // W1
    else n_new = (size_t)(f >> 6) * 128 + (part ? 64 : 0) + (f & 63);
    g_wt[dst + n_new * K0 + k] = __float2half_rn(W[rel]);
}

// ---------------------------------------------------------------------------
// L1 kernel: h1 = relu( Mix4x4 . (x @ W1) + b1 ), fp16 out. fp32 x direct.
// ---------------------------------------------------------------------------
__global__ __launch_bounds__(256, 2)
void l1_kernel(const float* __restrict__ X, const float* __restrict__ bias,
               __half* __restrict__ Out)
{
    extern __shared__ char smem[];
    const uint32_t sbase = smem_u32(smem);
    const int tid = threadIdx.x, wid = tid >> 5, lid = tid & 31;
    const int by = blockIdx.x, bm = blockIdx.y;
    const int warp_m = wid & 1, warp_n = wid >> 1;
    const int m_base = warp_m * 64, n_base = warp_n * 32;

    {
        const float* Xb = X + (size_t)bm * 128 * 64;
        #pragma unroll
        for (int i = 0; i < 8; ++i) {
            int c = tid + i * 256, r = c >> 4, q = c & 15;
            cp_async16(sbase + L1_OFFX + (uint32_t)(r * 68 + q * 4) * 4,
                       Xb + (size_t)r * 64 + q * 4);
        }
        const __half* Wb = g_wt + (size_t)by * 128 * 64;
        #pragma unroll
        for (int i = 0; i < 4; ++i) {
            int c = tid + i * 256, r = c >> 3, q = c & 7;
            cp_async16(sbase + L1_OFFW + (uint32_t)(r * PADK + q * 8) * 2,
                       Wb + (size_t)r * 64 + q * 8);
        }
        CP_COMMIT();
        CP_WAIT0();
    }
    __syncthreads();

    #pragma unroll
    for (int i = 0; i < 8; ++i) {
        int c = tid + i * 256, r = c >> 4, q = c & 15;
        float4 v = *(float4*)(smem + L1_OFFX + (r * 68 + q * 4) * 4);
        *(uint2*)(smem + L1_OFFA + (r * PADK + q * 4) * 2) =
            make_uint2(h2pack(v.x, v.y), h2pack(v.z, v.w));
    }
    __syncthreads();

    float acc[4][4][4];
    #pragma unroll
    for (int mt = 0; mt < 4; ++mt)
        #pragma unroll
        for (int nt = 0; nt < 4; ++nt)
            #pragma unroll
            for (int i = 0; i < 4; ++i) acc[mt][nt][i] = 0.f;

    const int a_r  = lid & 15;
    const int a_ko = (lid >> 4) << 3;
    const int b_r  = lid & 7;
    const int b_ko = (lid & 8);

    #pragma unroll
    for (int ks = 0; ks < 4; ++ks) {
        const int kof = ks * 16;
        uint32_t bh[4][2], af[4][4];
        #pragma unroll
        for (int nt = 0; nt < 4; ++nt) {
            uint32_t boff = (uint32_t)((n_base + nt * 8 + b_r) * PADK
                                       + kof + b_ko) * 2;
            ldsm_x2(bh[nt], sbase + L1_OFFW + boff);
        }
        #pragma unroll
        for (int mt = 0; mt < 4; ++mt) {
            uint32_t aoff = (uint32_t)((m_base + mt * 16 + a_r) * PADK
                                       + kof + a_ko) * 2;
            ldsm_x4(af[mt], sbase + L1_OFFA + aoff);
        }
        #pragma unroll
        for (int mt = 0; mt < 4; ++mt)
            #pragma unroll
            for (int nt = 0; nt < 4; ++nt)
                mma_f16(acc[mt][nt], af[mt], bh[nt][0], bh[nt][1]);
    }

    __syncthreads();
    {
        const int rq = lid >> 2, cq = (lid & 3) * 2;
        #pragma unroll
        for (int mt = 0; mt < 4; ++mt) {
            #pragma unroll
            for (int nt = 0; nt < 4; ++nt) {
                int col = n_base + nt * 8 + cq;
                int r0 = m_base + mt * 16 + rq;
                *(uint32_t*)(smem + L1_OFFX + (r0 * PADE + col) * 2) =
                    h2pack(acc[mt][nt][0], acc[mt][nt][1]);
                *(uint32_t*)(smem + L1_OFFX + ((r0 + 8) * PADE + col) * 2) =
                    h2pack(acc[mt][nt][2], acc[mt][nt][3]);
            }
        }
    }
    __syncthreads();

    float mat[16];
    #pragma unroll
    for (int i = 0; i < 16; ++i) mat[i] = g_A[i];
    #pragma unroll
    for (int it = 0; it < 2; ++it) {
        int item = it * 256 + tid;
        int b = item >> 4, ch = item & 15;
        int colg = by * 128 + ch * 8;
        float4 bv0 = *(const float4*)(bias + colg);
        float4 bv1 = *(const float4*)(bias + colg + 4);
        float bb[8] = {bv0.x, bv0.y, bv0.z, bv0.w, bv1.x, bv1.y, bv1.z, bv1.w};
        float v[4][8];
        #pragma unroll
        for (int m = 0; m < 4; ++m) {
            uint4 u = *(uint4*)(smem + L1_OFFX + ((b * 4 + m) * PADE + ch * 8) * 2);
            uint32_t* up = (uint32_t*)&u;
            #pragma unroll
            for (int q = 0; q < 4; ++q) {
                float2 f = __half22float2(*(__half2*)&up[q]);
                v[m][q * 2] = f.x; v[m][q * 2 + 1] = f.y;
            }
        }
        #pragma unroll
        for (int n = 0; n < 4; ++n) {
            uint32_t o[4];
            #pragma unroll
            for (int q = 0; q < 4; ++q) {
                float y0 = fmaxf(mat[n*4+0]*v[0][q*2]   + mat[n*4+1]*v[1][q*2]
                               + mat[n*4+2]*v[2][q*2]   + mat[n*4+3]*v[3][q*2]
                               + bb[q*2], 0.f);
                float y1 = fmaxf(mat[n*4+0]*v[0][q*2+1] + mat[n*4+1]*v[1][q*2+1]
                               + mat[n*4+2]*v[2][q*2+1] + mat[n*4+3]*v[3][q*2+1]
                               + bb[q*2+1], 0.f);
                o[q] = h2pack(y0, y1);
            }
            size_t row = (size_t)bm * 128 + b * 4 + n;
            *(uint4*)(Out + row * 1024 + colg) = *(uint4*)o;
        }
    }
}

// ---------------------------------------------------------------------------
// SAGE GEMM with fused mix epilogue. Weight tile rows = [Wl f..f+63 | Wr same].
// Output: y[M, Nout] fp16 (y = M.Pl + Pr + bias), ssq partials -> g_part[M][8].
// grid = (Nout/64, M/128).
// ---------------------------------------------------------------------------
__global__ __launch_bounds__(NTHREADS, 2)
void gemm_y_kernel(const __half* __restrict__ Ain, size_t w_off,
                   __half* __restrict__ Yout, const float* __restrict__ bias,
                   int K0, int Nout)
{
    extern __shared__ char smem[];
    const uint32_t sbase = smem_u32(smem);
    const int tid = threadIdx.x, wid = tid >> 5, lid = tid & 31;
    const int by = blockIdx.x, bm = blockIdx.y;
    const int warp_m = wid & 1, warp_n = wid >> 1;
    const int m_base = warp_m * 64, n_base = warp_n * 64;

    float acc[4][8][4];
    #pragma unroll
    for (int mt = 0; mt < 4; ++mt)
        #pragma unroll
        for (int nt = 0; nt < 8; ++nt)
            #pragma unroll
            for (int i = 0; i < 4; ++i) acc[mt][nt][i] = 0.f;

    const int a_r  = lid & 15;
    const int a_ko = (lid >> 4) << 3;
    const int b_n  = (lid & 7) + ((lid >> 4) << 3);
    const int b_ko = ((lid >> 3) & 1) << 3;

    const int KC = K0 >> 6;
    const __half* Ab = Ain + (size_t)bm * 128 * K0;
    const __half* Wb = g_wt + w_off + (size_t)by * 128 * K0;

    auto prefetch = [&](int kc) {
        uint32_t sb = sbase + (kc % STAGES) * STAGE_B;
        #pragma unroll
        for (int i = 0; i < 8; ++i) {
            int c = tid + i * NTHREADS, r = c >> 3, q = c & 7;
            cp_async16(sb + (uint32_t)(r * PADK + q * 8) * 2,
                       Ab + (size_t)r * K0 + (size_t)kc * 64 + q * 8);
        }
        #pragma unroll
        for (int i = 0; i < 8; ++i) {
            int c = tid + i * NTHREADS, r = c >> 3, q = c & 7;
            cp_async16(sb + TILE_A + (uint32_t)(r * PADK + q * 8) * 2,
                       Wb + (size_t)r * K0 + (size_t)kc * 64 + q * 8);
        }
        CP_COMMIT();
    };

    prefetch(0);
    if (KC > 1) prefetch(1); else CP_COMMIT();

    for (int kc = 0; kc < KC; ++kc) {
        CP_WAIT1();
        __syncthreads();
        if (kc + 2 < KC) prefetch(kc + 2); else CP_COMMIT();

        const uint32_t sb = sbase + (kc % STAGES) * STAGE_B;
        #pragma unroll
        for (int ks = 0; ks < 4; ++ks) {
            const int kof = ks * 16;
            uint32_t bf[4][4], af[4][4];
            #pragma unroll
            for (int p = 0; p < 4; ++p) {
                uint32_t boff = (uint32_t)((n_base + p * 16 + b_n) * PADK
                                           + kof + b_ko) * 2;
                ldsm_x4(bf[p], sb + TILE_A + boff);
            }
            #pragma unroll
            for (int mt = 0; mt < 4; ++mt) {
                uint32_t aoff = (uint32_t)((m_base + mt * 16 + a_r) * PADK
                                           + kof + a_ko) * 2;
                ldsm_x4(af[mt], sb + aoff);
            }
            #pragma unroll
            for (int mt = 0; mt < 4; ++mt)
                #pragma unroll
                for (int p = 0; p < 4; ++p) {
                    mma_f16(acc[mt][2 * p],     af[mt], bf[p][0], bf[p][1]);
                    mma_f16(acc[mt][2 * p + 1], af[mt], bf[p][2], bf[p][3]);
                }
        }
    }

    // ---- stage fp16 tile [128][PADE]; cols 0-63 = Pl part, 64-127 = Pr ----
    __syncthreads();
    float* sred = (float*)(smem + OFF_SRED);
    if (tid < 128) sred[tid] = 0.f;
    {
        const int rq = lid >> 2, cq = (lid & 3) * 2;
        #pragma unroll
        for (int mt = 0; mt < 4; ++mt) {
            #pragma unroll
            for (int nt = 0; nt < 8; ++nt) {
                int col = n_base + nt * 8 + cq;
                int r0 = m_base + mt * 16 + rq;
                *(uint32_t*)(smem + (r0 * PADE + col) * 2) =
                    h2pack(acc[mt][nt][0], acc[mt][nt][1]);
                *(uint32_t*)(smem + ((r0 + 8) * PADE + col) * 2) =
                    h2pack(acc[mt][nt][2], acc[mt][nt][3]);
            }
        }
    }
    __syncthreads();

    // ---- fused SAGE mix: y = M.C1 + C2 + bias, ssq partials ----
    float mat[16];
    #pragma unroll
    for (int i = 0; i < 16; ++i) mat[i] = g_M[i];
    #pragma unroll
    for (int it = 0; it < 2; ++it) {
        int item = it * NTHREADS + tid;     // 0..255 = 32 b x 8 ch
        int b = item >> 3, ch = item & 7;
        int c0 = ch * 8;
        int colg = by * 64 + c0;
        float4 bv0 = *(const float4*)(bias + colg);
        float4 bv1 = *(const float4*)(bias + colg + 4);
        float bb[8] = {bv0.x, bv0.y, bv0.z, bv0.w, bv1.x, bv1.y, bv1.z, bv1.w};
        float c1[4][8], c2[4][8];
        #pragma unroll
        for (int m = 0; m < 4; ++m) {
            uint4 u1 = *(uint4*)(smem + ((b * 4 + m) * PADE + c0) * 2);
            uint4 u2 = *(uint4*)(smem + ((b * 4 + m) * PADE + 64 + c0) * 2);
            uint32_t* p1 = (uint32_t*)&u1;
            uint32_t* p2 = (uint32_t*)&u2;
            #pragma unroll
            for (int q = 0; q < 4; ++q) {
                float2 f1 = __half22float2(*(__half2*)&p1[q]);
                float2 f2 = __half22float2(*(__half2*)&p2[q]);
                c1[m][q * 2] = f1.x; c1[m][q * 2 + 1] = f1.y;
                c2[m][q * 2] = f2.x; c2[m][q * 2 + 1] = f2.y;
            }
        }
        #pragma unroll
        for (int n = 0; n < 4; ++n) {
            uint32_t o[4];
            float ss = 0.f;
            #pragma unroll
            for (int q = 0; q < 4; ++q) {
                float y0 = mat[n*4+0]*c1[0][q*2]   + mat[n*4+1]*c1[1][q*2]
                         + mat[n*4+2]*c1[2][q*2]   + mat[n*4+3]*c1[3][q*2]
                         + c2[n][q*2]   + bb[q*2];
                float y1 = mat[n*4+0]*c1[0][q*2+1] + mat[n*4+1]*c1[1][q*2+1]
                         + mat[n*4+2]*c1[2][q*2+1] + mat[n*4+3]*c1[3][q*2+1]
                         + c2[n][q*2+1] + bb[q*2+1];
                ss += y0 * y0 + y1 * y1;
                o[q] = h2pack(y0, y1);
            }
            atomicAdd(&sred[b * 4 + n], ss);
            size_t row = (size_t)bm * 128 + b * 4 + n;
            *(uint4*)(Yout + row * Nout + colg) = *(uint4*)o;
        }
    }
    __syncthreads();
    if (tid < 128)
        g_part[((size_t)bm * 128 + tid) * 8 + by] = sred[tid];
}

// ---------------------------------------------------------------------------
// Normalize: h = relu( y * 1/max(sqrt(sum part),1e-12) ), fp16 -> g_hf.
// One thread per 8 elements. NT = number of column tiles (Nout/64).
// ---------------------------------------------------------------------------
__global__ __launch_bounds__(256)
void norm_kernel(const __half* __restrict__ Y, __half* __restrict__ H,
                 long long rows, int Nout, int NT)
{
    long long t8 = (long long)blockIdx.x * 256 + threadIdx.x;
    int cpr = Nout >> 3;                       // 8-elt chunks per row
    long long row = t8 / cpr;
    if (row >= rows) return;
    int c8 = (int)(t8 % cpr);

    const float* pp = g_part + row * 8;
    float ss = 0.f;
    for (int t = 0; t < NT; ++t) ss += pp[t];
    float inv = 1.f / fmaxf(sqrtf(ss), 1e-12f);

    size_t e = (size_t)row * Nout + c8 * 8;
    uint4 u = *(const uint4*)(Y + e);
    uint32_t* up = (uint32_t*)&u;
    uint32_t o[4];
    #pragma unroll
    for (int q = 0; q < 4; ++q) {
        float2 f = __half22float2(*(__half2*)&up[q]);
        o[q] = h2pack(fmaxf(f.x * inv, 0.f), fmaxf(f.y * inv, 0.f));
    }
    *(uint4*)(H + e) = *(uint4*)o;
}

// ---------------------------------------------------------------------------
// Fused L4 normalize + FC + softmax. y4 [M,256] + part sums (NT=4).
// 4 batches per 256-thread block; 64 threads per batch.
// ---------------------------------------------------------------------------
__global__ __launch_bounds__(256)
void sage_fc_kernel(const __half* __restrict__ Y,
                    const float* __restrict__ Wfc,
                    const float* __restrict__ bfc,
                    float* __restrict__ out)
{
    __shared__ float sW[10240];
    __shared__ float lred[4][2][10];
    const int tid = threadIdx.x;
    for (int i = tid; i < 10240; i += 256) sW[i] = Wfc[i];

    const int sub = tid >> 6, stid = tid & 63;
    const long long b = (long long)blockIdx.x * 4 + sub;
    const int lane = stid & 31, wis = stid >> 5;

    const size_t Yb = (size_t)b * 4 * 256;
    const int f = stid * 4;

    float inv[4];
    #pragma unroll
    for (int n = 0; n < 4; ++n) {
        const float* pp = g_part + ((size_t)b * 4 + n) * 8;
        float ss = pp[0] + pp[1] + pp[2] + pp[3];
        inv[n] = 1.f / fmaxf(sqrtf(ss), 1e-12f);
    }
    __syncthreads();   // sW ready

    float part[10];
    #pragma unroll
    for (int o = 0; o < 10; ++o) part[o] = 0.f;
    #pragma unroll
    for (int n = 0; n < 4; ++n) {
        float4 y = load_h4(Y, Yb + (size_t)n * 256 + f);
        float hv[4] = {fmaxf(y.x * inv[n], 0.f), fmaxf(y.y * inv[n], 0.f),
                       fmaxf(y.z * inv[n], 0.f), fmaxf(y.w * inv[n], 0.f)};
        #pragma unroll
        for (int j = 0; j < 4; ++j) {
            int k = n * 256 + f + j;
            const float* w = sW + k * 10;
            #pragma unroll
            for (int o = 0; o < 10; ++o) part[o] += hv[j] * w[o];
        }
    }
    #pragma unroll
    for (int o = 0; o < 10; ++o)
        #pragma unroll
        for (int off = 16; off > 0; off >>= 1)
            part[o] += __shfl_xor_sync(0xffffffffu, part[o], off);
    if (lane == 0) {
        #pragma unroll
        for (int o = 0; o < 10; ++o) lred[sub][wis][o] = part[o];
    }
    __syncthreads();

    if (stid == 0) {
        float logit[10], m = -1e30f;
        #pragma unroll
        for (int o = 0; o < 10; ++o) {
            logit[o] = lred[sub][0][o] + lred[sub][1][o] + bfc[o];
            m = fmaxf(m, logit[o]);
        }
        float s = 0.f;
        #pragma unroll
        for (int o = 0; o < 10; ++o) { logit[o] = expf(logit[o] - m); s += logit[o]; }
        float invs = 1.f / s;
        float* orow = out + (size_t)b * 10;
        #pragma unroll
        for (int o = 0; o < 10; ++o) orow[o] = logit[o] * invs;
    }
}

// ---------------------------------------------------------------------------
extern "C" void kernel_launch(void* const* d_in, const int* in_sizes, int n_in,
                              void* d_out, int out_size)
{
    const float* x   = (const float*)d_in[0];
    const void*  ei  = d_in[1];
    const float* W1  = (const float*)d_in[2];
    const float* b1  = (const float*)d_in[3];
    const float* Wl2 = (const float*)d_in[4];
    const float* bl2 = (const float*)d_in[5];
    const float* Wr2 = (const float*)d_in[6];
    const float* Wl3 = (const float*)d_in[7];
    const float* bl3 = (const float*)d_in[8];
    const float* Wr3 = (const float*)d_in[9];
    const float* Wl4 = (const float*)d_in[10];
    const float* bl4 = (const float*)d_in[11];
    const float* Wr4 = (const float*)d_in[12];
    const float* Wfc = (const float*)d_in[13];
    const float* bfc = (const float*)d_in[14];

    const int B = in_sizes[0] / (4 * 64);
    const int E = in_sizes[1] / 2;
    const long long M = (long long)B * 4;

    __half *Pf, *hf;
    cudaGetSymbolAddress((void**)&Pf, g_Pf);
    cudaGetSymbolAddress((void**)&hf, g_hf);

    cudaFuncSetAttribute(gemm_y_kernel,
                         cudaFuncAttributeMaxDynamicSharedMemorySize, SMEM_BYTES);
    cudaFuncSetAttribute(l1_kernel,
                         cudaFuncAttributeMaxDynamicSharedMemorySize, L1_SMEM);

    build_graph_kernel<<<1, 32>>>(ei, E);
    prep_all_kernel<<<(1507328 + 255) / 256, 256>>>(W1, Wl2, Wr2, Wl3, Wr3, Wl4, Wr4);

    // weight offsets (fp16 elems): W1@0; L2 interleaved @65536 (1024x1024);
    // L3 interleaved @1114112 (512x512); L4 interleaved @1376256 (512x256)
    const size_t OW2 = 65536, OW3 = 1114112, OW4 = 1376256;
    const unsigned gm = (unsigned)(M / 128);

    // L1: h1 = relu(Mix.(x@W1) + b1) -> g_hf [M,1024]
    l1_kernel<<<dim3(8, gm), 256, L1_SMEM>>>(x, b1, hf);
    // L2: y2 = M.(h1@Wl2) + h1@Wr2 + bl2 -> g_Pf [M,512] (+ssq); normalize
    gemm_y_kernel<<<dim3(8, gm), NTHREADS, SMEM_BYTES>>>(hf, OW2, Pf, bl2, 1024, 512);
    norm_kernel<<<(unsigned)((M * 64 + 255) / 256), 256>>>(Pf, hf, M, 512, 8);
    // L3: y3 -> g_Pf [M,256]; normalize -> g_hf [M,256]
    gemm_y_kernel<<<dim3(4, gm), NTHREADS, SMEM_BYTES>>>(hf, OW3, Pf, bl3, 512, 256);
    norm_kernel<<<(unsigned)((M * 32 + 255) / 256), 256>>>(Pf, hf, M, 256, 4);
    // L4: y4 -> g_Pf [M,256]; fused normalize + FC + softmax
    gemm_y_kernel<<<dim3(4, gm), NTHREADS, SMEM_BYTES>>>(hf, OW4, Pf, bl4, 256, 256);
    sage_fc_kernel<<<B / 4, 256>>>(Pf, Wfc, bfc, (float*)d_out);
}

// round 16
// speedup vs baseline: 1.0460x; 1.0460x over previous
#include <cuda_runtime.h>
#include <cuda_fp16.h>
#include <math.h>
#include <stdint.h>

// ===========================================================================
// GNN over fixed 4-node graph, B=32768 (M = 4B = 131072 rows).
// L2-L4 GEMM (champion config): mma.sync fp16->fp32, CTA 128x128, 4 warps
// (2x2) of 64x64, 2 CTAs/SM, 3-stage cp.async, batched ldsm per ks.
// Dedicated L1 kernel (fp32 x direct, fused GCN). SAGE-L4+FC+softmax fused.
// sage_post uint4-vectorized (8 halves/thread).
// ===========================================================================

#define MAXB 32768
#define PADK 72
#define TILE_A (128 * PADK * 2)
#define TILE_W (128 * PADK * 2)
#define STAGE_B (TILE_A + TILE_W)
#define STAGES 3
#define SMEM_BYTES (STAGES * STAGE_B)   // 110592 -> 2 CTAs/SM
#define PADE 136
#define NTHREADS 128

#define L1_OFFX 0
#define L1_OFFA 34816
#define L1_OFFW (34816 + 18432)
#define L1_SMEM (L1_OFFW + 18432)

__device__ float g_A[16];
__device__ float g_M[16];
__device__ __align__(16) __half g_Pf[(size_t)MAXB * 4 * 1024];
__device__ __align__(16) __half g_hf[(size_t)MAXB * 4 * 1024];
__device__ __align__(16) __half g_wt[1507328];

// ---------------------------------------------------------------------------
__device__ __forceinline__ uint32_t smem_u32(const void* p) {
    uint32_t a;
    asm("{ .reg .u64 t; cvta.to.shared.u64 t, %1; cvt.u32.u64 %0, t; }"
        : "=r"(a) : "l"(p));
    return a;
}
__device__ __forceinline__ void ldsm_x4(uint32_t (&r)[4], uint32_t addr) {
    asm volatile("ldmatrix.sync.aligned.m8n8.x4.shared.b16 {%0,%1,%2,%3}, [%4];"
                 : "=r"(r[0]), "=r"(r[1]), "=r"(r[2]), "=r"(r[3]) : "r"(addr));
}
__device__ __forceinline__ void ldsm_x2(uint32_t (&r)[2], uint32_t addr) {
    asm volatile("ldmatrix.sync.aligned.m8n8.x2.shared.b16 {%0,%1}, [%2];"
                 : "=r"(r[0]), "=r"(r[1]) : "r"(addr));
}
__device__ __forceinline__ void mma_f16(float (&d)[4], const uint32_t (&a)[4],
                                        uint32_t b0, uint32_t b1) {
    asm volatile(
        "mma.sync.aligned.m16n8k16.row.col.f32.f16.f16.f32 "
        "{%0,%1,%2,%3}, {%4,%5,%6,%7}, {%8,%9}, {%0,%1,%2,%3};"
        : "+f"(d[0]), "+f"(d[1]), "+f"(d[2]), "+f"(d[3])
        : "r"(a[0]), "r"(a[1]), "r"(a[2]), "r"(a[3]), "r"(b0), "r"(b1));
}
__device__ __forceinline__ void cp_async16(uint32_t dst, const void* src) {
    asm volatile("cp.async.cg.shared.global [%0], [%1], 16;"
                 :: "r"(dst), "l"(src));
}
#define CP_COMMIT() asm volatile("cp.async.commit_group;" ::: "memory")
#define CP_WAIT0()  asm volatile("cp.async.wait_group 0;" ::: "memory")
#define CP_WAIT1()  asm volatile("cp.async.wait_group 1;" ::: "memory")

__device__ __forceinline__ uint32_t h2pack(float a, float b) {
    __half2 h = __floats2half2_rn(a, b);
    return *(uint32_t*)&h;
}
__device__ __forceinline__ float4 load_h4(const __half* H, size_t e) {
    uint2 u = *(const uint2*)(H + e);
    __half2 p0 = *(__half2*)&u.x, p1 = *(__half2*)&u.y;
    float2 a = __half22float2(p0), b = __half22float2(p1);
    return make_float4(a.x, a.y, b.x, b.y);
}
// load 8 consecutive fp16 as 8 floats
__device__ __forceinline__ void load_h8(const __half* H, size_t e, float (&o)[8]) {
    uint4 u = *(const uint4*)(H + e);
    uint32_t* up = (uint32_t*)&u;
    #pragma unroll
    for (int q = 0; q < 4; ++q) {
        float2 f = __half22float2(*(__half2*)&up[q]);
        o[q * 2] = f.x; o[q * 2 + 1] = f.y;
    }
}

// ---------------------------------------------------------------------------
__global__ void build_graph_kernel(const void* __restrict__ ei_raw, int E)
{
    if (threadIdx.x != 0 || blockIdx.x != 0) return;
    const long long* e64 = (const long long*)ei_raw;
    const int*       e32 = (const int*)ei_raw;
    bool is64 = true;
    for (int e = 0; e < E; ++e) {
        long long v = e64[e];
        if (v < 0 || v >= 4) { is64 = false; break; }
    }
    int src[64], dst[64];
    for (int e = 0; e < E; ++e) {
        if (is64) { src[e] = (int)e64[e]; dst[e] = (int)e64[E + e]; }
        else      { src[e] = e32[e];      dst[e] = e32[E + e]; }
    }
    float degG[4] = {1.f, 1.f, 1.f, 1.f};
    float cntS[4] = {0.f, 0.f, 0.f, 0.f};
    for (int e = 0; e < E; ++e) { degG[dst[e]] += 1.f; cntS[dst[e]] += 1.f; }
    float dinv[4];
    #pragma unroll
    for (int n = 0; n < 4; ++n) dinv[n] = rsqrtf(degG[n]);
    float A[16], M[16];
    #pragma unroll
    for (int i = 0; i < 16; ++i) { A[i] = 0.f; M[i] = 0.f; }
    for (int e = 0; e < E; ++e) {
        int s = src[e], d = dst[e];
        A[d * 4 + s] += dinv[s] * dinv[d];
        M[d * 4 + s] += 1.f / fmaxf(cntS[d], 1.f);
    }
    #pragma unroll
    for (int n = 0; n < 4; ++n) A[n * 4 + n] += dinv[n] * dinv[n];
    #pragma unroll
    for (int i = 0; i < 16; ++i) { g_A[i] = A[i]; g_M[i] = M[i]; }
}

// ---------------------------------------------------------------------------
__global__ void prep_all_kernel(const float* __restrict__ W1,
                                const float* __restrict__ Wl2,
                                const float* __restrict__ Wr2,
                                const float* __restrict__ Wl3,
                                const float* __restrict__ Wr3,
                                const float* __restrict__ Wl4,
                                const float* __restrict__ Wr4)
{
    long long idx = (long long)blockIdx.x * 256 + threadIdx.x;
    if (idx >= 1507328LL) return;
    const float* W; int K0, N; size_t dst; long long rel;
    if      (idx < 65536)   { W = W1;  K0 = 64;   N = 1024; dst = 0;       rel = idx; }
    else if (idx < 589824)  { W = Wl2; K0 = 1024; N = 512;  dst = 65536;   rel = idx - 65536; }
    else if (idx < 1114112) { W = Wr2; K0 = 1024; N = 512;  dst = 589824;  rel = idx - 589824; }
    else if (idx < 1245184) { W = Wl3; K0 = 512;  N = 256;  dst = 1114112; rel = idx - 1114112; }
    else if (idx < 1376256) { W = Wr3; K0 = 512;  N = 256;  dst = 1245184; rel = idx - 1245184; }
    else if (idx < 1441792) { W = Wl4; K0 = 256;  N = 256;  dst = 1376256; rel = idx - 1376256; }
    else                    { W = Wr4; K0 = 256;  N = 256;  dst = 1441792; rel = idx - 1441792; }
    int k = (int)(rel / N), n = (int)(rel % N);
    g_wt[dst + (size_t)n * K0 + k] = __float2half_rn(W[rel]);
}

// ---------------------------------------------------------------------------
// L1 kernel: h1 = relu( Mix4x4 . (x @ W1) + b1 ), fp16 out. fp32 x direct.
// ---------------------------------------------------------------------------
__global__ __launch_bounds__(256, 2)
void l1_kernel(const float* __restrict__ X, const float* __restrict__ bias,
               __half* __restrict__ Out)
{
    extern __shared__ char smem[];
    const uint32_t sbase = smem_u32(smem);
    const int tid = threadIdx.x, wid = tid >> 5, lid = tid & 31;
    const int by = blockIdx.x, bm = blockIdx.y;
    const int warp_m = wid & 1, warp_n = wid >> 1;
    const int m_base = warp_m * 64, n_base = warp_n * 32;

    {
        const float* Xb = X + (size_t)bm * 128 * 64;
        #pragma unroll
        for (int i = 0; i < 8; ++i) {
            int c = tid + i * 256, r = c >> 4, q = c & 15;
            cp_async16(sbase + L1_OFFX + (uint32_t)(r * 68 + q * 4) * 4,
                       Xb + (size_t)r * 64 + q * 4);
        }
        const __half* Wb = g_wt + (size_t)by * 128 * 64;
        #pragma unroll
        for (int i = 0; i < 4; ++i) {
            int c = tid + i * 256, r = c >> 3, q = c & 7;
            cp_async16(sbase + L1_OFFW + (uint32_t)(r * PADK + q * 8) * 2,
                       Wb + (size_t)r * 64 + q * 8);
        }
        CP_COMMIT();
        CP_WAIT0();
    }
    __syncthreads();

    #pragma unroll
    for (int i = 0; i < 8; ++i) {
        int c = tid + i * 256, r = c >> 4, q = c & 15;
        float4 v = *(float4*)(smem + L1_OFFX + (r * 68 + q * 4) * 4);
        *(uint2*)(smem + L1_OFFA + (r * PADK + q * 4) * 2) =
            make_uint2(h2pack(v.x, v.y), h2pack(v.z, v.w));
    }
    __syncthreads();

    float acc[4][4][4];
    #pragma unroll
    for (int mt = 0; mt < 4; ++mt)
        #pragma unroll
        for (int nt = 0; nt < 4; ++nt)
            #pragma unroll
            for (int i = 0; i < 4; ++i) acc[mt][nt][i] = 0.f;

    const int a_r  = lid & 15;
    const int a_ko = (lid >> 4) << 3;
    const int b_r  = lid & 7;
    const int b_ko = (lid & 8);

    #pragma unroll
    for (int ks = 0; ks < 4; ++ks) {
        const int kof = ks * 16;
        uint32_t bh[4][2], af[4][4];
        #pragma unroll
        for (int nt = 0; nt < 4; ++nt) {
            uint32_t boff = (uint32_t)((n_base + nt * 8 + b_r) * PADK
                                       + kof + b_ko) * 2;
            ldsm_x2(bh[nt], sbase + L1_OFFW + boff);
        }
        #pragma unroll
        for (int mt = 0; mt < 4; ++mt) {
            uint32_t aoff = (uint32_t)((m_base + mt * 16 + a_r) * PADK
                                       + kof + a_ko) * 2;
            ldsm_x4(af[mt], sbase + L1_OFFA + aoff);
        }
        #pragma unroll
        for (int mt = 0; mt < 4; ++mt)
            #pragma unroll
            for (int nt = 0; nt < 4; ++nt)
                mma_f16(acc[mt][nt], af[mt], bh[nt][0], bh[nt][1]);
    }

    __syncthreads();
    {
        const int rq = lid >> 2, cq = (lid & 3) * 2;
        #pragma unroll
        for (int mt = 0; mt < 4; ++mt) {
            #pragma unroll
            for (int nt = 0; nt < 4; ++nt) {
                int col = n_base + nt * 8 + cq;
                int r0 = m_base + mt * 16 + rq;
                *(uint32_t*)(smem + L1_OFFX + (r0 * PADE + col) * 2) =
                    h2pack(acc[mt][nt][0], acc[mt][nt][1]);
                *(uint32_t*)(smem + L1_OFFX + ((r0 + 8) * PADE + col) * 2) =
                    h2pack(acc[mt][nt][2], acc[mt][nt][3]);
            }
        }
    }
    __syncthreads();

    float mat[16];
    #pragma unroll
    for (int i = 0; i < 16; ++i) mat[i] = g_A[i];
    #pragma unroll
    for (int it = 0; it < 2; ++it) {
        int item = it * 256 + tid;
        int b = item >> 4, ch = item & 15;
        int colg = by * 128 + ch * 8;
        float4 bv0 = *(const float4*)(bias + colg);
        float4 bv1 = *(const float4*)(bias + colg + 4);
        float bb[8] = {bv0.x, bv0.y, bv0.z, bv0.w, bv1.x, bv1.y, bv1.z, bv1.w};
        float v[4][8];
        #pragma unroll
        for (int m = 0; m < 4; ++m) {
            uint4 u = *(uint4*)(smem + L1_OFFX + ((b * 4 + m) * PADE + ch * 8) * 2);
            uint32_t* up = (uint32_t*)&u;
            #pragma unroll
            for (int q = 0; q < 4; ++q) {
                float2 f = __half22float2(*(__half2*)&up[q]);
                v[m][q * 2] = f.x; v[m][q * 2 + 1] = f.y;
            }
        }
        #pragma unroll
        for (int n = 0; n < 4; ++n) {
            uint32_t o[4];
            #pragma unroll
            for (int q = 0; q < 4; ++q) {
                float y0 = fmaxf(mat[n*4+0]*v[0][q*2]   + mat[n*4+1]*v[1][q*2]
                               + mat[n*4+2]*v[2][q*2]   + mat[n*4+3]*v[3][q*2]
                               + bb[q*2], 0.f);
                float y1 = fmaxf(mat[n*4+0]*v[0][q*2+1] + mat[n*4+1]*v[1][q*2+1]
                               + mat[n*4+2]*v[2][q*2+1] + mat[n*4+3]*v[3][q*2+1]
                               + bb[q*2+1], 0.f);
                o[q] = h2pack(y0, y1);
            }
            size_t row = (size_t)bm * 128 + b * 4 + n;
            *(uint4*)(Out + row * 1024 + colg) = *(uint4*)o;
        }
    }
}

// ---------------------------------------------------------------------------
// fp16 GEMM (L2-L4): CTA 128x128, 4 warps (2x2) of 64x64, 3-stage cp.async.
// ---------------------------------------------------------------------------
__global__ __launch_bounds__(NTHREADS, 2)
void gemm_tc_kernel(const __half* __restrict__ Ain, size_t w_off,
                    __half* __restrict__ Out, int K0, int Ntot)
{
    extern __shared__ char smem[];
    const uint32_t sbase = smem_u32(smem);
    const int tid = threadIdx.x, wid = tid >> 5, lid = tid & 31;
    const int by = blockIdx.x, bm = blockIdx.y;
    const int warp_m = wid & 1, warp_n = wid >> 1;
    const int m_base = warp_m * 64, n_base = warp_n * 64;

    float acc[4][8][4];
    #pragma unroll
    for (int mt = 0; mt < 4; ++mt)
        #pragma unroll
        for (int nt = 0; nt < 8; ++nt)
            #pragma unroll
            for (int i = 0; i < 4; ++i) acc[mt][nt][i] = 0.f;

    const int a_r  = lid & 15;
    const int a_ko = (lid >> 4) << 3;
    const int b_n  = (lid & 7) + ((lid >> 4) << 3);
    const int b_ko = ((lid >> 3) & 1) << 3;

    const int KC = K0 >> 6;
    const __half* Ab = Ain + (size_t)bm * 128 * K0;
    const __half* Wb = g_wt + w_off + (size_t)by * 128 * K0;

    auto prefetch = [&](int kc) {
        uint32_t sb = sbase + (kc % STAGES) * STAGE_B;
        #pragma unroll
        for (int i = 0; i < 8; ++i) {
            int c = tid + i * NTHREADS, r = c >> 3, q = c & 7;
            cp_async16(sb + (uint32_t)(r * PADK + q * 8) * 2,
                       Ab + (size_t)r * K0 + (size_t)kc * 64 + q * 8);
        }
        #pragma unroll
        for (int i = 0; i < 8; ++i) {
            int c = tid + i * NTHREADS, r = c >> 3, q = c & 7;
            cp_async16(sb + TILE_A + (uint32_t)(r * PADK + q * 8) * 2,
                       Wb + (size_t)r * K0 + (size_t)kc * 64 + q * 8);
        }
        CP_COMMIT();
    };

    prefetch(0);
    if (KC > 1) prefetch(1); else CP_COMMIT();

    for (int kc = 0; kc < KC; ++kc) {
        CP_WAIT1();
        __syncthreads();
        if (kc + 2 < KC) prefetch(kc + 2); else CP_COMMIT();

        const uint32_t sb = sbase + (kc % STAGES) * STAGE_B;
        #pragma unroll
        for (int ks = 0; ks < 4; ++ks) {
            const int kof = ks * 16;
            uint32_t bf[4][4], af[4][4];
            #pragma unroll
            for (int p = 0; p < 4; ++p) {
                uint32_t boff = (uint32_t)((n_base + p * 16 + b_n) * PADK
                                           + kof + b_ko) * 2;
                ldsm_x4(bf[p], sb + TILE_A + boff);
            }
            #pragma unroll
            for (int mt = 0; mt < 4; ++mt) {
                uint32_t aoff = (uint32_t)((m_base + mt * 16 + a_r) * PADK
                                           + kof + a_ko) * 2;
                ldsm_x4(af[mt], sb + aoff);
            }
            #pragma unroll
            for (int mt = 0; mt < 4; ++mt)
                #pragma unroll
                for (int p = 0; p < 4; ++p) {
                    mma_f16(acc[mt][2 * p],     af[mt], bf[p][0], bf[p][1]);
                    mma_f16(acc[mt][2 * p + 1], af[mt], bf[p][2], bf[p][3]);
                }
        }
    }

    __syncthreads();
    {
        const int rq = lid >> 2, cq = (lid & 3) * 2;
        #pragma unroll
        for (int mt = 0; mt < 4; ++mt) {
            #pragma unroll
            for (int nt = 0; nt < 8; ++nt) {
                int col = n_base + nt * 8 + cq;
                int r0 = m_base + mt * 16 + rq;
                *(uint32_t*)(smem + (r0 * PADE + col) * 2) =
                    h2pack(acc[mt][nt][0], acc[mt][nt][1]);
                *(uint32_t*)(smem + ((r0 + 8) * PADE + col) * 2) =
                    h2pack(acc[mt][nt][2], acc[mt][nt][3]);
            }
        }
    }
    __syncthreads();

    const int rbase = tid >> 4, cg = (tid & 15) * 8;
    #pragma unroll
    for (int it = 0; it < 16; ++it) {
        int row = rbase + it * 8;
        uint4 v = *(uint4*)(smem + (row * PADE + cg) * 2);
        *(uint4*)(Out + ((size_t)bm * 128 + row) * Ntot
                      + (size_t)by * 128 + cg) = v;
    }
}

// ---------------------------------------------------------------------------
// SAGE post (L2/L3), uint4-vectorized: G batches per 256-thread block,
// spt = N/8 threads per batch. h = relu(l2norm(Mix.Pl + Pr + bias)).
// ---------------------------------------------------------------------------
__global__ __launch_bounds__(256)
void sage_post_kernel(const float* __restrict__ bias, int N, int G)
{
    __shared__ float red[8][4][2];
    const int tid = threadIdx.x;
    const int spt = N >> 3;                  // 64 (N=512) or 32 (N=256)
    const int sub = tid / spt, stid = tid % spt;
    const long long b = (long long)blockIdx.x * G + sub;
    const int lane = stid & 31, wis = stid >> 5, nws = spt >> 5;

    float mat[16];
    #pragma unroll
    for (int i = 0; i < 16; ++i) mat[i] = g_M[i];

    const size_t Pb = (size_t)b * 4 * (2 * N);
    const int f = stid * 8;
    float pl[4][8];
    #pragma unroll
    for (int m = 0; m < 4; ++m)
        load_h8(g_Pf, Pb + (size_t)m * 2 * N + f, pl[m]);
    float4 bv0 = *(const float4*)(bias + f);
    float4 bv1 = *(const float4*)(bias + f + 4);
    float bb[8] = {bv0.x, bv0.y, bv0.z, bv0.w, bv1.x, bv1.y, bv1.z, bv1.w};

    float y[4][8];
    float ss[4];
    #pragma unroll
    for (int n = 0; n < 4; ++n) {
        float pr[8];
        load_h8(g_Pf, Pb + (size_t)n * 2 * N + N + f, pr);
        float s = 0.f;
        #pragma unroll
        for (int j = 0; j < 8; ++j) {
            float r = mat[n*4+0]*pl[0][j] + mat[n*4+1]*pl[1][j]
                    + mat[n*4+2]*pl[2][j] + mat[n*4+3]*pl[3][j]
                    + pr[j] + bb[j];
            y[n][j] = r;
            s += r * r;
        }
        ss[n] = s;
    }
    #pragma unroll
    for (int n = 0; n < 4; ++n)
        #pragma unroll
        for (int off = 16; off > 0; off >>= 1)
            ss[n] += __shfl_xor_sync(0xffffffffu, ss[n], off);
    if (lane == 0) {
        #pragma unroll
        for (int n = 0; n < 4; ++n) red[sub][n][wis] = ss[n];
    }
    __syncthreads();
    float inv[4];
    #pragma unroll
    for (int n = 0; n < 4; ++n) {
        float t = 0.f;
        for (int w = 0; w < nws; ++w) t += red[sub][n][w];
        inv[n] = 1.f / fmaxf(sqrtf(t), 1e-12f);
    }
    #pragma unroll
    for (int n = 0; n < 4; ++n) {
        uint32_t o[4];
        #pragma unroll
        for (int q = 0; q < 4; ++q)
            o[q] = h2pack(fmaxf(y[n][q*2] * inv[n], 0.f),
                          fmaxf(y[n][q*2+1] * inv[n], 0.f));
        *(uint4*)(g_hf + (size_t)(b * 4 + n) * N + f) = *(uint4*)o;
    }
}

// ---------------------------------------------------------------------------
// Fused SAGE-L4 post + FC + softmax. 4 batches per 256-thread block.
// ---------------------------------------------------------------------------
__global__ __launch_bounds__(256)
void sage_fc_kernel(const float* __restrict__ bias,
                    const float* __restrict__ Wfc,
                    const float* __restrict__ bfc,
                    float* __restrict__ out)
{
    __shared__ float sW[10240];
    __shared__ float red[4][4][2];
    __shared__ float lred[4][2][10];
    const int tid = threadIdx.x;
    for (int i = tid; i < 10240; i += 256) sW[i] = Wfc[i];

    const int sub = tid >> 6, stid = tid & 63;
    const long long b = (long long)blockIdx.x * 4 + sub;
    const int lane = stid & 31, wis = stid >> 5;

    float mat[16];
    #pragma unroll
    for (int i = 0; i < 16; ++i) mat[i] = g_M[i];

    const size_t Pb = (size_t)b * 4 * 512;
    const int f = stid * 4;
    float4 pl[4];
    #pragma unroll
    for (int m = 0; m < 4; ++m)
        pl[m] = load_h4(g_Pf, Pb + (size_t)m * 512 + f);
    float4 bv = *(const float4*)(bias + f);

    float4 y[4];
    float ss[4];
    #pragma unroll
    for (int n = 0; n < 4; ++n) {
        float4 pr = load_h4(g_Pf, Pb + (size_t)n * 512 + 256 + f);
        float4 r;
        r.x = mat[n*4+0]*pl[0].x + mat[n*4+1]*pl[1].x + mat[n*4+2]*pl[2].x + mat[n*4+3]*pl[3].x + pr.x + bv.x;
        r.y = mat[n*4+0]*pl[0].y + mat[n*4+1]*pl[1].y + mat[n*4+2]*pl[2].y + mat[n*4+3]*pl[3].y + pr.y + bv.y;
        r.z = mat[n*4+0]*pl[0].z + mat[n*4+1]*pl[1].z + mat[n*4+2]*pl[2].z + mat[n*4+3]*pl[3].z + pr.z + bv.z;
        r.w = mat[n*4+0]*pl[0].w + mat[n*4+1]*pl[1].w + mat[n*4+2]*pl[2].w + mat[n*4+3]*pl[3].w + pr.w + bv.w;
        y[n] = r;
        ss[n] = r.x * r.x + r.y * r.y + r.z * r.z + r.w * r.w;
    }
    #pragma unroll
    for (int n = 0; n < 4; ++n)
        #pragma unroll
        for (int off = 16; off > 0; off >>= 1)
            ss[n] += __shfl_xor_sync(0xffffffffu, ss[n], off);
    if (lane == 0) {
        #pragma unroll
        for (int n = 0; n < 4; ++n) red[sub][n][wis] = ss[n];
    }
    __syncthreads();

    float part[10];
    #pragma unroll
    for (int o = 0; o < 10; ++o) part[o] = 0.f;
    #pragma unroll
    for (int n = 0; n < 4; ++n) {
        float inv = 1.f / fmaxf(sqrtf(red[sub][n][0] + red[sub][n][1]), 1e-12f);
        float hv[4] = {fmaxf(y[n].x * inv, 0.f), fmaxf(y[n].y * inv, 0.f),
                       fmaxf(y[n].z * inv, 0.f), fmaxf(y[n].w * inv, 0.f)};
        #pragma unroll
        for (int j = 0; j < 4; ++j) {
            int k = n * 256 + f + j;
            const float* w = sW + k * 10;
            #pragma unroll
            for (int o = 0; o < 10; ++o) part[o] += hv[j] * w[o];
        }
    }
    #pragma unroll
    for (int o = 0; o < 10; ++o)
        #pragma unroll
        for (int off = 16; off > 0; off >>= 1)
            part[o] += __shfl_xor_sync(0xffffffffu, part[o], off);
    if (lane == 0) {
        #pragma unroll
        for (int o = 0; o < 10; ++o) lred[sub][wis][o] = part[o];
    }
    __syncthreads();

    if (stid == 0) {
        float logit[10], m = -1e30f;
        #pragma unroll
        for (int o = 0; o < 10; ++o) {
            logit[o] = lred[sub][0][o] + lred[sub][1][o] + bfc[o];
            m = fmaxf(m, logit[o]);
        }
        float s = 0.f;
        #pragma unroll
        for (int o = 0; o < 10; ++o) { logit[o] = expf(logit[o] - m); s += logit[o]; }
        float invs = 1.f / s;
        float* orow = out + (size_t)b * 10;
        #pragma unroll
        for (int o = 0; o < 10; ++o) orow[o] = logit[o] * invs;
    }
}

// ---------------------------------------------------------------------------
extern "C" void kernel_launch(void* const* d_in, const int* in_sizes, int n_in,
                              void* d_out, int out_size)
{
    const float* x   = (const float*)d_in[0];
    const void*  ei  = d_in[1];
    const float* W1  = (const float*)d_in[2];
    const float* b1  = (const float*)d_in[3];
    const float* Wl2 = (const float*)d_in[4];
    const float* bl2 = (const float*)d_in[5];
    const float* Wr2 = (const float*)d_in[6];
    const float* Wl3 = (const float*)d_in[7];
    const float* bl3 = (const float*)d_in[8];
    const float* Wr3 = (const float*)d_in[9];
    const float* Wl4 = (const float*)d_in[10];
    const float* bl4 = (const float*)d_in[11];
    const float* Wr4 = (const float*)d_in[12];
    const float* Wfc = (const float*)d_in[13];
    const float* bfc = (const float*)d_in[14];

    const int B = in_sizes[0] / (4 * 64);
    const int E = in_sizes[1] / 2;
    const long long M = (long long)B * 4;

    __half *Pf, *hf;
    cudaGetSymbolAddress((void**)&Pf, g_Pf);
    cudaGetSymbolAddress((void**)&hf, g_hf);

    cudaFuncSetAttribute(gemm_tc_kernel,
                         cudaFuncAttributeMaxDynamicSharedMemorySize, SMEM_BYTES);
    cudaFuncSetAttribute(l1_kernel,
                         cudaFuncAttributeMaxDynamicSharedMemorySize, L1_SMEM);

    build_graph_kernel<<<1, 32>>>(ei, E);
    prep_all_kernel<<<(1507328 + 255) / 256, 256>>>(W1, Wl2, Wr2, Wl3, Wr3, Wl4, Wr4);

    const size_t OW2 = 65536, OW3 = 1114112, OW4 = 1376256;
    const unsigned gm = (unsigned)(M / 128);

    // L1: h1 = relu(Mix.(x@W1) + b1)
    l1_kernel<<<dim3(8, gm), 256, L1_SMEM>>>(x, b1, hf);
    // L2: P2 = h1 @ [Wl2|Wr2] [M,1024];  h2 = sage_post(P2) [M,512]
    gemm_tc_kernel<<<dim3(8, gm), NTHREADS, SMEM_BYTES>>>(hf, OW2, Pf, 1024, 1024);
    sage_post_kernel<<<B / 4, 256>>>(bl2, 512, 4);
    // L3: P3 = h2 @ [Wl3|Wr3] [M,512];  h3 [M,256]
    gemm_tc_kernel<<<dim3(4, gm), NTHREADS, SMEM_BYTES>>>(hf, OW3, Pf, 512, 512);
    sage_post_kernel<<<B / 8, 256>>>(bl3, 256, 8);
    // L4: P4 = h3 @ [Wl4|Wr4] [M,512]; fused SAGE post + FC + softmax
    gemm_tc_kernel<<<dim3(4, gm), NTHREADS, SMEM_BYTES>>>(hf, OW4, Pf, 256, 512);
    sage_fc_kernel<<<B / 4, 256>>>(bl4, Wfc, bfc, (float*)d_out);
}

// round 17
// speedup vs baseline: 1.0462x; 1.0001x over previous
#include <cuda_runtime.h>
#include <cuda_fp16.h>
#include <math.h>
#include <stdint.h>

// ===========================================================================
// GNN over fixed 4-node graph, B=32768 (M = 4B = 131072 rows).
// L2-L4 GEMM (champion config): mma.sync fp16->fp32, CTA 128x128, 4 warps
// (2x2) of 64x64, 2 CTAs/SM, 3-stage cp.async, batched ldsm per ks.
// Dedicated L1 kernel (fp32 x direct, fused GCN). SAGE-L4+FC+softmax fused
// (8 batches / 512-thread block). sage_post uint4-vectorized.
// ===========================================================================

#define MAXB 32768
#define PADK 72
#define TILE_A (128 * PADK * 2)
#define TILE_W (128 * PADK * 2)
#define STAGE_B (TILE_A + TILE_W)
#define STAGES 3
#define SMEM_BYTES (STAGES * STAGE_B)   // 110592 -> 2 CTAs/SM
#define PADE 136
#define NTHREADS 128

#define L1_OFFX 0
#define L1_OFFA 34816
#define L1_OFFW (34816 + 18432)
#define L1_SMEM (L1_OFFW + 18432)

__device__ float g_A[16];
__device__ float g_M[16];
__device__ __align__(16) __half g_Pf[(size_t)MAXB * 4 * 1024];
__device__ __align__(16) __half g_hf[(size_t)MAXB * 4 * 1024];
__device__ __align__(16) __half g_wt[1507328];

// ---------------------------------------------------------------------------
__device__ __forceinline__ uint32_t smem_u32(const void* p) {
    uint32_t a;
    asm("{ .reg .u64 t; cvta.to.shared.u64 t, %1; cvt.u32.u64 %0, t; }"
        : "=r"(a) : "l"(p));
    return a;
}
__device__ __forceinline__ void ldsm_x4(uint32_t (&r)[4], uint32_t addr) {
    asm volatile("ldmatrix.sync.aligned.m8n8.x4.shared.b16 {%0,%1,%2,%3}, [%4];"
                 : "=r"(r[0]), "=r"(r[1]), "=r"(r[2]), "=r"(r[3]) : "r"(addr));
}
__device__ __forceinline__ void ldsm_x2(uint32_t (&r)[2], uint32_t addr) {
    asm volatile("ldmatrix.sync.aligned.m8n8.x2.shared.b16 {%0,%1}, [%2];"
                 : "=r"(r[0]), "=r"(r[1]) : "r"(addr));
}
__device__ __forceinline__ void mma_f16(float (&d)[4], const uint32_t (&a)[4],
                                        uint32_t b0, uint32_t b1) {
    asm volatile(
        "mma.sync.aligned.m16n8k16.row.col.f32.f16.f16.f32 "
        "{%0,%1,%2,%3}, {%4,%5,%6,%7}, {%8,%9}, {%0,%1,%2,%3};"
        : "+f"(d[0]), "+f"(d[1]), "+f"(d[2]), "+f"(d[3])
        : "r"(a[0]), "r"(a[1]), "r"(a[2]), "r"(a[3]), "r"(b0), "r"(b1));
}
__device__ __forceinline__ void cp_async16(uint32_t dst, const void* src) {
    asm volatile("cp.async.cg.shared.global [%0], [%1], 16;"
                 :: "r"(dst), "l"(src));
}
#define CP_COMMIT() asm volatile("cp.async.commit_group;" ::: "memory")
#define CP_WAIT0()  asm volatile("cp.async.wait_group 0;" ::: "memory")
#define CP_WAIT1()  asm volatile("cp.async.wait_group 1;" ::: "memory")

__device__ __forceinline__ uint32_t h2pack(float a, float b) {
    __half2 h = __floats2half2_rn(a, b);
    return *(uint32_t*)&h;
}
__device__ __forceinline__ float4 load_h4(const __half* H, size_t e) {
    uint2 u = *(const uint2*)(H + e);
    __half2 p0 = *(__half2*)&u.x, p1 = *(__half2*)&u.y;
    float2 a = __half22float2(p0), b = __half22float2(p1);
    return make_float4(a.x, a.y, b.x, b.y);
}
__device__ __forceinline__ void load_h8(const __half* H, size_t e, float (&o)[8]) {
    uint4 u = *(const uint4*)(H + e);
    uint32_t* up = (uint32_t*)&u;
    #pragma unroll
    for (int q = 0; q < 4; ++q) {
        float2 f = __half22float2(*(__half2*)&up[q]);
        o[q * 2] = f.x; o[q * 2 + 1] = f.y;
    }
}

// ---------------------------------------------------------------------------
__global__ void build_graph_kernel(const void* __restrict__ ei_raw, int E)
{
    if (threadIdx.x != 0 || blockIdx.x != 0) return;
    const long long* e64 = (const long long*)ei_raw;
    const int*       e32 = (const int*)ei_raw;
    bool is64 = true;
    for (int e = 0; e < E; ++e) {
        long long v = e64[e];
        if (v < 0 || v >= 4) { is64 = false; break; }
    }
    int src[64], dst[64];
    for (int e = 0; e < E; ++e) {
        if (is64) { src[e] = (int)e64[e]; dst[e] = (int)e64[E + e]; }
        else      { src[e] = e32[e];      dst[e] = e32[E + e]; }
    }
    float degG[4] = {1.f, 1.f, 1.f, 1.f};
    float cntS[4] = {0.f, 0.f, 0.f, 0.f};
    for (int e = 0; e < E; ++e) { degG[dst[e]] += 1.f; cntS[dst[e]] += 1.f; }
    float dinv[4];
    #pragma unroll
    for (int n = 0; n < 4; ++n) dinv[n] = rsqrtf(degG[n]);
    float A[16], M[16];
    #pragma unroll
    for (int i = 0; i < 16; ++i) { A[i] = 0.f; M[i] = 0.f; }
    for (int e = 0; e < E; ++e) {
        int s = src[e], d = dst[e];
        A[d * 4 + s] += dinv[s] * dinv[d];
        M[d * 4 + s] += 1.f / fmaxf(cntS[d], 1.f);
    }
    #pragma unroll
    for (int n = 0; n < 4; ++n) A[n * 4 + n] += dinv[n] * dinv[n];
    #pragma unroll
    for (int i = 0; i < 16; ++i) { g_A[i] = A[i]; g_M[i] = M[i]; }
}

// ---------------------------------------------------------------------------
__global__ void prep_all_kernel(const float* __restrict__ W1,
                                const float* __restrict__ Wl2,
                                const float* __restrict__ Wr2,
                                const float* __restrict__ Wl3,
                                const float* __restrict__ Wr3,
                                const float* __restrict__ Wl4,
                                const float* __restrict__ Wr4)
{
    long long idx = (long long)blockIdx.x * 256 + threadIdx.x;
    if (idx >= 1507328LL) return;
    const float* W; int K0, N; size_t dst; long long rel;
    if      (idx < 65536)   { W = W1;  K0 = 64;   N = 1024; dst = 0;       rel = idx; }
    else if (idx < 589824)  { W = Wl2; K0 = 1024; N = 512;  dst = 65536;   rel = idx - 65536; }
    else if (idx < 1114112) { W = Wr2; K0 = 1024; N = 512;  dst = 589824;  rel = idx - 589824; }
    else if (idx < 1245184) { W = Wl3; K0 = 512;  N = 256;  dst = 1114112; rel = idx - 1114112; }
    else if (idx < 1376256) { W = Wr3; K0 = 512;  N = 256;  dst = 1245184; rel = idx - 1245184; }
    else if (idx < 1441792) { W = Wl4; K0 = 256;  N = 256;  dst = 1376256; rel = idx - 1376256; }
    else                    { W = Wr4; K0 = 256;  N = 256;  dst = 1441792; rel = idx - 1441792; }
    int k = (int)(rel / N), n = (int)(rel % N);
    g_wt[dst + (size_t)n * K0 + k] = __float2half_rn(W[rel]);
}

// ---------------------------------------------------------------------------
// L1 kernel: h1 = relu( Mix4x4 . (x @ W1) + b1 ), fp16 out. fp32 x direct.
// ---------------------------------------------------------------------------
__global__ __launch_bounds__(256, 2)
void l1_kernel(const float* __restrict__ X, const float* __restrict__ bias,
               __half* __restrict__ Out)
{
    extern __shared__ char smem[];
    const uint32_t sbase = smem_u32(smem);
    const int tid = threadIdx.x, wid = tid >> 5, lid = tid & 31;
    const int by = blockIdx.x, bm = blockIdx.y;
    const int warp_m = wid & 1, warp_n = wid >> 1;
    const int m_base = warp_m * 64, n_base = warp_n * 32;

    {
        const float* Xb = X + (size_t)bm * 128 * 64;
        #pragma unroll
        for (int i = 0; i < 8; ++i) {
            int c = tid + i * 256, r = c >> 4, q = c & 15;
            cp_async16(sbase + L1_OFFX + (uint32_t)(r * 68 + q * 4) * 4,
                       Xb + (size_t)r * 64 + q * 4);
        }
        const __half* Wb = g_wt + (size_t)by * 128 * 64;
        #pragma unroll
        for (int i = 0; i < 4; ++i) {
            int c = tid + i * 256, r = c >> 3, q = c & 7;
            cp_async16(sbase + L1_OFFW + (uint32_t)(r * PADK + q * 8) * 2,
                       Wb + (size_t)r * 64 + q * 8);
        }
        CP_COMMIT();
        CP_WAIT0();
    }
    __syncthreads();

    #pragma unroll
    for (int i = 0; i < 8; ++i) {
        int c = tid + i * 256, r = c >> 4, q = c & 15;
        float4 v = *(float4*)(smem + L1_OFFX + (r * 68 + q * 4) * 4);
        *(uint2*)(smem + L1_OFFA + (r * PADK + q * 4) * 2) =
            make_uint2(h2pack(v.x, v.y), h2pack(v.z, v.w));
    }
    __syncthreads();

    float acc[4][4][4];
    #pragma unroll
    for (int mt = 0; mt < 4; ++mt)
        #pragma unroll
        for (int nt = 0; nt < 4; ++nt)
            #pragma unroll
            for (int i = 0; i < 4; ++i) acc[mt][nt][i] = 0.f;

    const int a_r  = lid & 15;
    const int a_ko = (lid >> 4) << 3;
    const int b_r  = lid & 7;
    const int b_ko = (lid & 8);

    #pragma unroll
    for (int ks = 0; ks < 4; ++ks) {
        const int kof = ks * 16;
        uint32_t bh[4][2], af[4][4];
        #pragma unroll
        for (int nt = 0; nt < 4; ++nt) {
            uint32_t boff = (uint32_t)((n_base + nt * 8 + b_r) * PADK
                                       + kof + b_ko) * 2;
            ldsm_x2(bh[nt], sbase + L1_OFFW + boff);
        }
        #pragma unroll
        for (int mt = 0; mt < 4; ++mt) {
            uint32_t aoff = (uint32_t)((m_base + mt * 16 + a_r) * PADK
                                       + kof + a_ko) * 2;
            ldsm_x4(af[mt], sbase + L1_OFFA + aoff);
        }
        #pragma unroll
        for (int mt = 0; mt < 4; ++mt)
            #pragma unroll
            for (int nt = 0; nt < 4; ++nt)
                mma_f16(acc[mt][nt], af[mt], bh[nt][0], bh[nt][1]);
    }

    __syncthreads();
    {
        const int rq = lid >> 2, cq = (lid & 3) * 2;
        #pragma unroll
        for (int mt = 0; mt < 4; ++mt) {
            #pragma unroll
            for (int nt = 0; nt < 4; ++nt) {
                int col = n_base + nt * 8 + cq;
                int r0 = m_base + mt * 16 + rq;
                *(uint32_t*)(smem + L1_OFFX + (r0 * PADE + col) * 2) =
                    h2pack(acc[mt][nt][0], acc[mt][nt][1]);
                *(uint32_t*)(smem + L1_OFFX + ((r0 + 8) * PADE + col) * 2) =
                    h2pack(acc[mt][nt][2], acc[mt][nt][3]);
            }
        }
    }
    __syncthreads();

    float mat[16];
    #pragma unroll
    for (int i = 0; i < 16; ++i) mat[i] = g_A[i];
    #pragma unroll
    for (int it = 0; it < 2; ++it) {
        int item = it * 256 + tid;
        int b = item >> 4, ch = item & 15;
        int colg = by * 128 + ch * 8;
        float4 bv0 = *(const float4*)(bias + colg);
        float4 bv1 = *(const float4*)(bias + colg + 4);
        float bb[8] = {bv0.x, bv0.y, bv0.z, bv0.w, bv1.x, bv1.y, bv1.z, bv1.w};
        float v[4][8];
        #pragma unroll
        for (int m = 0; m < 4; ++m) {
            uint4 u = *(uint4*)(smem + L1_OFFX + ((b * 4 + m) * PADE + ch * 8) * 2);
            uint32_t* up = (uint32_t*)&u;
            #pragma unroll
            for (int q = 0; q < 4; ++q) {
                float2 f = __half22float2(*(__half2*)&up[q]);
                v[m][q * 2] = f.x; v[m][q * 2 + 1] = f.y;
            }
        }
        #pragma unroll
        for (int n = 0; n < 4; ++n) {
            uint32_t o[4];
            #pragma unroll
            for (int q = 0; q < 4; ++q) {
                float y0 = fmaxf(mat[n*4+0]*v[0][q*2]   + mat[n*4+1]*v[1][q*2]
                               + mat[n*4+2]*v[2][q*2]   + mat[n*4+3]*v[3][q*2]
                               + bb[q*2], 0.f);
                float y1 = fmaxf(mat[n*4+0]*v[0][q*2+1] + mat[n*4+1]*v[1][q*2+1]
                               + mat[n*4+2]*v[2][q*2+1] + mat[n*4+3]*v[3][q*2+1]
                               + bb[q*2+1], 0.f);
                o[q] = h2pack(y0, y1);
            }
            size_t row = (size_t)bm * 128 + b * 4 + n;
            *(uint4*)(Out + row * 1024 + colg) = *(uint4*)o;
        }
    }
}

// ---------------------------------------------------------------------------
// fp16 GEMM (L2-L4): CTA 128x128, 4 warps (2x2) of 64x64, 3-stage cp.async.
// ---------------------------------------------------------------------------
__global__ __launch_bounds__(NTHREADS, 2)
void gemm_tc_kernel(const __half* __restrict__ Ain, size_t w_off,
                    __half* __restrict__ Out, int K0, int Ntot)
{
    extern __shared__ char smem[];
    const uint32_t sbase = smem_u32(smem);
    const int tid = threadIdx.x, wid = tid >> 5, lid = tid & 31;
    const int by = blockIdx.x, bm = blockIdx.y;
    const int warp_m = wid & 1, warp_n = wid >> 1;
    const int m_base = warp_m * 64, n_base = warp_n * 64;

    float acc[4][8][4];
    #pragma unroll
    for (int mt = 0; mt < 4; ++mt)
        #pragma unroll
        for (int nt = 0; nt < 8; ++nt)
            #pragma unroll
            for (int i = 0; i < 4; ++i) acc[mt][nt][i] = 0.f;

    const int a_r  = lid & 15;
    const int a_ko = (lid >> 4) << 3;
    const int b_n  = (lid & 7) + ((lid >> 4) << 3);
    const int b_ko = ((lid >> 3) & 1) << 3;

    const int KC = K0 >> 6;
    const __half* Ab = Ain + (size_t)bm * 128 * K0;
    const __half* Wb = g_wt + w_off + (size_t)by * 128 * K0;

    auto prefetch = [&](int kc) {
        uint32_t sb = sbase + (kc % STAGES) * STAGE_B;
        #pragma unroll
        for (int i = 0; i < 8; ++i) {
            int c = tid + i * NTHREADS, r = c >> 3, q = c & 7;
            cp_async16(sb + (uint32_t)(r * PADK + q * 8) * 2,
                       Ab + (size_t)r * K0 + (size_t)kc * 64 + q * 8);
        }
        #pragma unroll
        for (int i = 0; i < 8; ++i) {
            int c = tid + i * NTHREADS, r = c >> 3, q = c & 7;
            cp_async16(sb + TILE_A + (uint32_t)(r * PADK + q * 8) * 2,
                       Wb + (size_t)r * K0 + (size_t)kc * 64 + q * 8);
        }
        CP_COMMIT();
    };

    prefetch(0);
    if (KC > 1) prefetch(1); else CP_COMMIT();

    for (int kc = 0; kc < KC; ++kc) {
        CP_WAIT1();
        __syncthreads();
        if (kc + 2 < KC) prefetch(kc + 2); else CP_COMMIT();

        const uint32_t sb = sbase + (kc % STAGES) * STAGE_B;
        #pragma unroll
        for (int ks = 0; ks < 4; ++ks) {
            const int kof = ks * 16;
            uint32_t bf[4][4], af[4][4];
            #pragma unroll
            for (int p = 0; p < 4; ++p) {
                uint32_t boff = (uint32_t)((n_base + p * 16 + b_n) * PADK
                                           + kof + b_ko) * 2;
                ldsm_x4(bf[p], sb + TILE_A + boff);
            }
            #pragma unroll
            for (int mt = 0; mt < 4; ++mt) {
                uint32_t aoff = (uint32_t)((m_base + mt * 16 + a_r) * PADK
                                           + kof + a_ko) * 2;
                ldsm_x4(af[mt], sb + aoff);
            }
            #pragma unroll
            for (int mt = 0; mt < 4; ++mt)
                #pragma unroll
                for (int p = 0; p < 4; ++p) {
                    mma_f16(acc[mt][2 * p],     af[mt], bf[p][0], bf[p][1]);
                    mma_f16(acc[mt][2 * p + 1], af[mt], bf[p][2], bf[p][3]);
                }
        }
    }

    __syncthreads();
    {
        const int rq = lid >> 2, cq = (lid & 3) * 2;
        #pragma unroll
        for (int mt = 0; mt < 4; ++mt) {
            #pragma unroll
            for (int nt = 0; nt < 8; ++nt) {
                int col = n_base + nt * 8 + cq;
                int r0 = m_base + mt * 16 + rq;
                *(uint32_t*)(smem + (r0 * PADE + col) * 2) =
                    h2pack(acc[mt][nt][0], acc[mt][nt][1]);
                *(uint32_t*)(smem + ((r0 + 8) * PADE + col) * 2) =
                    h2pack(acc[mt][nt][2], acc[mt][nt][3]);
            }
        }
    }
    __syncthreads();

    const int rbase = tid >> 4, cg = (tid & 15) * 8;
    #pragma unroll
    for (int it = 0; it < 16; ++it) {
        int row = rbase + it * 8;
        uint4 v = *(uint4*)(smem + (row * PADE + cg) * 2);
        *(uint4*)(Out + ((size_t)bm * 128 + row) * Ntot
                      + (size_t)by * 128 + cg) = v;
    }
}

// ---------------------------------------------------------------------------
// SAGE post (L2/L3), uint4-vectorized: G batches per 256-thread block.
// ---------------------------------------------------------------------------
__global__ __launch_bounds__(256)
void sage_post_kernel(const float* __restrict__ bias, int N, int G)
{
    __shared__ float red[8][4][2];
    const int tid = threadIdx.x;
    const int spt = N >> 3;
    const int sub = tid / spt, stid = tid % spt;
    const long long b = (long long)blockIdx.x * G + sub;
    const int lane = stid & 31, wis = stid >> 5, nws = spt >> 5;

    float mat[16];
    #pragma unroll
    for (int i = 0; i < 16; ++i) mat[i] = g_M[i];

    const size_t Pb = (size_t)b * 4 * (2 * N);
    const int f = stid * 8;
    float pl[4][8];
    #pragma unroll
    for (int m = 0; m < 4; ++m)
        load_h8(g_Pf, Pb + (size_t)m * 2 * N + f, pl[m]);
    float4 bv0 = *(const float4*)(bias + f);
    float4 bv1 = *(const float4*)(bias + f + 4);
    float bb[8] = {bv0.x, bv0.y, bv0.z, bv0.w, bv1.x, bv1.y, bv1.z, bv1.w};

    float y[4][8];
    float ss[4];
    #pragma unroll
    for (int n = 0; n < 4; ++n) {
        float pr[8];
        load_h8(g_Pf, Pb + (size_t)n * 2 * N + N + f, pr);
        float s = 0.f;
        #pragma unroll
        for (int j = 0; j < 8; ++j) {
            float r = mat[n*4+0]*pl[0][j] + mat[n*4+1]*pl[1][j]
                    + mat[n*4+2]*pl[2][j] + mat[n*4+3]*pl[3][j]
                    + pr[j] + bb[j];
            y[n][j] = r;
            s += r * r;
        }
        ss[n] = s;
    }
    #pragma unroll
    for (int n = 0; n < 4; ++n)
        #pragma unroll
        for (int off = 16; off > 0; off >>= 1)
            ss[n] += __shfl_xor_sync(0xffffffffu, ss[n], off);
    if (lane == 0) {
        #pragma unroll
        for (int n = 0; n < 4; ++n) red[sub][n][wis] = ss[n];
    }
    __syncthreads();
    float inv[4];
    #pragma unroll
    for (int n = 0; n < 4; ++n) {
        float t = 0.f;
        for (int w = 0; w < nws; ++w) t += red[sub][n][w];
        inv[n] = 1.f / fmaxf(sqrtf(t), 1e-12f);
    }
    #pragma unroll
    for (int n = 0; n < 4; ++n) {
        uint32_t o[4];
        #pragma unroll
        for (int q = 0; q < 4; ++q)
            o[q] = h2pack(fmaxf(y[n][q*2] * inv[n], 0.f),
                          fmaxf(y[n][q*2+1] * inv[n], 0.f));
        *(uint4*)(g_hf + (size_t)(b * 4 + n) * N + f) = *(uint4*)o;
    }
}

// ---------------------------------------------------------------------------
// Fused SAGE-L4 post + FC + softmax. 8 batches per 512-thread block
// (halves Wfc L2 traffic vs 4/256).
// ---------------------------------------------------------------------------
__global__ __launch_bounds__(512)
void sage_fc_kernel(const float* __restrict__ bias,
                    const float* __restrict__ Wfc,
                    const float* __restrict__ bfc,
                    float* __restrict__ out)
{
    __shared__ float sW[10240];
    __shared__ float red[8][4][2];
    __shared__ float lred[8][2][10];
    const int tid = threadIdx.x;
    for (int i = tid; i < 10240; i += 512) sW[i] = Wfc[i];

    const int sub = tid >> 6, stid = tid & 63;     // 8 subs x 64 threads
    const long long b = (long long)blockIdx.x * 8 + sub;
    const int lane = stid & 31, wis = stid >> 5;

    float mat[16];
    #pragma unroll
    for (int i = 0; i < 16; ++i) mat[i] = g_M[i];

    const size_t Pb = (size_t)b * 4 * 512;
    const int f = stid * 4;
    float4 pl[4];
    #pragma unroll
    for (int m = 0; m < 4; ++m)
        pl[m] = load_h4(g_Pf, Pb + (size_t)m * 512 + f);
    float4 bv = *(const float4*)(bias + f);

    float4 y[4];
    float ss[4];
    #pragma unroll
    for (int n = 0; n < 4; ++n) {
        float4 pr = load_h4(g_Pf, Pb + (size_t)n * 512 + 256 + f);
        float4 r;
        r.x = mat[n*4+0]*pl[0].x + mat[n*4+1]*pl[1].x + mat[n*4+2]*pl[2].x + mat[n*4+3]*pl[3].x + pr.x + bv.x;
        r.y = mat[n*4+0]*pl[0].y + mat[n*4+1]*pl[1].y + mat[n*4+2]*pl[2].y + mat[n*4+3]*pl[3].y + pr.y + bv.y;
        r.z = mat[n*4+0]*pl[0].z + mat[n*4+1]*pl[1].z + mat[n*4+2]*pl[2].z + mat[n*4+3]*pl[3].z + pr.z + bv.z;
        r.w = mat[n*4+0]*pl[0].w + mat[n*4+1]*pl[1].w + mat[n*4+2]*pl[2].w + mat[n*4+3]*pl[3].w + pr.w + bv.w;
        y[n] = r;
        ss[n] = r.x * r.x + r.y * r.y + r.z * r.z + r.w * r.w;
    }
    #pragma unroll
    for (int n = 0; n < 4; ++n)
        #pragma unroll
        for (int off = 16; off > 0; off >>= 1)
            ss[n] += __shfl_xor_sync(0xffffffffu, ss[n], off);
    if (lane == 0) {
        #pragma unroll
        for (int n = 0; n < 4; ++n) red[sub][n][wis] = ss[n];
    }
    __syncthreads();   // red visible AND sW loaded

    float part[10];
    #pragma unroll
    for (int o = 0; o < 10; ++o) part[o] = 0.f;
    #pragma unroll
    for (int n = 0; n < 4; ++n) {
        float inv = 1.f / fmaxf(sqrtf(red[sub][n][0] + red[sub][n][1]), 1e-12f);
        float hv[4] = {fmaxf(y[n].x * inv, 0.f), fmaxf(y[n].y * inv, 0.f),
                       fmaxf(y[n].z * inv, 0.f), fmaxf(y[n].w * inv, 0.f)};
        #pragma unroll
        for (int j = 0; j < 4; ++j) {
            int k = n * 256 + f + j;
            const float* w = sW + k * 10;
            #pragma unroll
            for (int o = 0; o < 10; ++o) part[o] += hv[j] * w[o];
        }
    }
    #pragma unroll
    for (int o = 0; o < 10; ++o)
        #pragma unroll
        for (int off = 16; off > 0; off >>= 1)
            part[o] += __shfl_xor_sync(0xffffffffu, part[o], off);
    if (lane == 0) {
        #pragma unroll
        for (int o = 0; o < 10; ++o) lred[sub][wis][o] = part[o];
    }
    __syncthreads();

    if (stid == 0) {
        float logit[10], m = -1e30f;
        #pragma unroll
        for (int o = 0; o < 10; ++o) {
            logit[o] = lred[sub][0][o] + lred[sub][1][o] + bfc[o];
            m = fmaxf(m, logit[o]);
        }
        float s = 0.f;
        #pragma unroll
        for (int o = 0; o < 10; ++o) { logit[o] = expf(logit[o] - m); s += logit[o]; }
        float invs = 1.f / s;
        float* orow = out + (size_t)b * 10;
        #pragma unroll
        for (int o = 0; o < 10; ++o) orow[o] = logit[o] * invs;
    }
}

// ---------------------------------------------------------------------------
extern "C" void kernel_launch(void* const* d_in, const int* in_sizes, int n_in,
                              void* d_out, int out_size)
{
    const float* x   = (const float*)d_in[0];
    const void*  ei  = d_in[1];
    const float* W1  = (const float*)d_in[2];
    const float* b1  = (const float*)d_in[3];
    const float* Wl2 = (const float*)d_in[4];
    const float* bl2 = (const float*)d_in[5];
    const float* Wr2 = (const float*)d_in[6];
    const float* Wl3 = (const float*)d_in[7];
    const float* bl3 = (const float*)d_in[8];
    const float* Wr3 = (const float*)d_in[9];
    const float* Wl4 = (const float*)d_in[10];
    const float* bl4 = (const float*)d_in[11];
    const float* Wr4 = (const float*)d_in[12];
    const float* Wfc = (const float*)d_in[13];
    const float* bfc = (const float*)d_in[14];

    const int B = in_sizes[0] / (4 * 64);
    const int E = in_sizes[1] / 2;
    const long long M = (long long)B * 4;

    __half *Pf, *hf;
    cudaGetSymbolAddress((void**)&Pf, g_Pf);
    cudaGetSymbolAddress((void**)&hf, g_hf);

    cudaFuncSetAttribute(gemm_tc_kernel,
                         cudaFuncAttributeMaxDynamicSharedMemorySize, SMEM_BYTES);
    cudaFuncSetAttribute(l1_kernel,
                         cudaFuncAttributeMaxDynamicSharedMemorySize, L1_SMEM);

    build_graph_kernel<<<1, 32>>>(ei, E);
    prep_all_kernel<<<(1507328 + 255) / 256, 256>>>(W1, Wl2, Wr2, Wl3, Wr3, Wl4, Wr4);

    const size_t OW2 = 65536, OW3 = 1114112, OW4 = 1376256;
    const unsigned gm = (unsigned)(M / 128);

    // L1: h1 = relu(Mix.(x@W1) + b1)
    l1_kernel<<<dim3(8, gm), 256, L1_SMEM>>>(x, b1, hf);
    // L2: P2 = h1 @ [Wl2|Wr2] [M,1024];  h2 = sage_post(P2) [M,512]
    gemm_tc_kernel<<<dim3(8, gm), NTHREADS, SMEM_BYTES>>>(hf, OW2, Pf, 1024, 1024);
    sage_post_kernel<<<B / 4, 256>>>(bl2, 512, 4);
    // L3: P3 = h2 @ [Wl3|Wr3] [M,512];  h3 [M,256]
    gemm_tc_kernel<<<dim3(4, gm), NTHREADS, SMEM_BYTES>>>(hf, OW3, Pf, 512, 512);
    sage_post_kernel<<<B / 8, 256>>>(bl3, 256, 8);
    // L4: P4 = h3 @ [Wl4|Wr4] [M,512]; fused SAGE post + FC + softmax
    gemm_tc_kernel<<<dim3(4, gm), NTHREADS, SMEM_BYTES>>>(hf, OW4, Pf, 256, 512);
    sage_fc_kernel<<<B / 8, 512>>>(bl4, Wfc, bfc, (float*)d_out);
}